// round 4
// baseline (speedup 1.0000x reference)
#include <cuda_runtime.h>
#include <cuda_bf16.h>
#include <cstdint>

#define T_ 256
#define B_ 64
#define E_ 512
#define H_ 512
#define KT 32
#define G4 2048
#define TB (T_*B_)
#define NEGV -100000.0f
#define RB 64            // blocks per direction in recurrence

typedef __nv_bfloat16 bf16;

// ---------------- static device scratch ----------------
__device__ bf16  g_x0b[(size_t)TB*E_];           // embedded input bf16 [tb][512]
__device__ bf16  g_x1b[(size_t)TB*2*H_];         // layer0 out bf16 [tb][1024]
__device__ bf16  g_x2b[(size_t)TB*2*H_];         // layer1 out bf16 [tb][1024]
__device__ float g_xp[(size_t)2*TB*G4];          // input-proj gates fp32 [d][tb][g]
__device__ bf16  g_hb[(size_t)2*B_*H_];          // recurrent h bf16 [d][b][k]
__device__ bf16  g_wih0b[(size_t)2*G4*E_];
__device__ bf16  g_whh0b[(size_t)2*G4*H_];
__device__ bf16  g_wih1b[(size_t)2*G4*2*H_];
__device__ bf16  g_whh1b[(size_t)2*G4*H_];
__device__ bf16  g_lwb[(size_t)KT*2*H_];
__device__ float g_feats[(size_t)TB*KT];
__device__ float g_part[B_];
__device__ unsigned g_bar_cnt[2];
__device__ unsigned g_bar_gen[2];

// ---------------- helpers ----------------
__device__ __forceinline__ void mma_bf(float* c, uint32_t a0, uint32_t a1,
                                       uint32_t a2, uint32_t a3,
                                       uint32_t b0, uint32_t b1)
{
    asm volatile(
        "mma.sync.aligned.m16n8k16.row.col.f32.bf16.bf16.f32 "
        "{%0,%1,%2,%3},{%4,%5,%6,%7},{%8,%9},{%0,%1,%2,%3};"
        : "+f"(c[0]), "+f"(c[1]), "+f"(c[2]), "+f"(c[3])
        : "r"(a0), "r"(a1), "r"(a2), "r"(a3), "r"(b0), "r"(b1));
}

__device__ __forceinline__ void cpa16(uint32_t dst, const void* src) {
    asm volatile("cp.async.cg.shared.global [%0], [%1], 16;" :: "r"(dst), "l"(src));
}
#define CP_COMMIT asm volatile("cp.async.commit_group;")
#define CP_WAIT(n) asm volatile("cp.async.wait_group %0;" :: "n"(n))

__device__ __forceinline__ float sigf(float x) { return 1.f / (1.f + __expf(-x)); }

// grid barrier among the RB blocks of one direction
__device__ __forceinline__ void gbarrier(int d, unsigned& bgen) {
    __syncthreads();
    if (threadIdx.x == 0) {
        __threadfence();
        if (atomicAdd(&g_bar_cnt[d], 1u) == RB - 1u) {
            atomicExch(&g_bar_cnt[d], 0u);
            __threadfence();
            atomicExch(&g_bar_gen[d], bgen + 1u);
        } else {
            while (*((volatile unsigned*)&g_bar_gen[d]) == bgen) __nanosleep(32);
        }
        __threadfence();
    }
    bgen++;
    __syncthreads();
}

// ---------------- weight conversion fp32 -> bf16 ----------------
__global__ void cvtall_k(const float* __restrict__ wih0, const float* __restrict__ whh0,
                         const float* __restrict__ wih1, const float* __restrict__ whh1,
                         const float* __restrict__ lw)
{
    int i = blockIdx.x * 256 + threadIdx.x;   // float4 index
    const float* s; bf16* dst; int off;
    if      (i <  524288) { s = wih0; dst = g_wih0b; off = i; }
    else if (i < 1048576) { s = whh0; dst = g_whh0b; off = i -  524288; }
    else if (i < 2097152) { s = wih1; dst = g_wih1b; off = i - 1048576; }
    else if (i < 2621440) { s = whh1; dst = g_whh1b; off = i - 2097152; }
    else if (i < 2629632) { s = lw;   dst = g_lwb;   off = i - 2621440; }
    else return;
    float4 v = ((const float4*)s)[off];
    __nv_bfloat162* o = (__nv_bfloat162*)dst + (size_t)off * 2;
    o[0] = __floats2bfloat162_rn(v.x, v.y);
    o[1] = __floats2bfloat162_rn(v.z, v.w);
}

// ---------------- embedding lookup -> bf16 ----------------
__global__ void embed_k(const int* __restrict__ tokens, const float* __restrict__ embed) {
    size_t i = (size_t)blockIdx.x * 256 + threadIdx.x;  // float4 index
    size_t el = i * 4;
    size_t tb = el >> 9;
    int    e  = (int)(el & 511);
    float4 v = *(const float4*)(embed + (size_t)tokens[tb] * E_ + e);
    __nv_bfloat162* o = (__nv_bfloat162*)(g_x0b + el);
    o[0] = __floats2bfloat162_rn(v.x, v.y);
    o[1] = __floats2bfloat162_rn(v.z, v.w);
}

// ---------------- input projection: xp[d][tb][g] = X[tb][:] . W[g][:] + bias ----
// block tile 128(tb) x 128(g), K-chunk 32, double-buffered cp.async
template<int L>
__global__ __launch_bounds__(256) void gemm_k(const bf16* __restrict__ W,
                                              const float* __restrict__ bias)
{
    constexpr int KSZ = (L == 0) ? 512 : 1024;
    constexpr int NC  = KSZ / 32;
    const bf16* X = (L == 0) ? g_x0b : g_x1b;

    __shared__ __align__(16) bf16 As[2][128 * 40];
    __shared__ __align__(16) bf16 Bs[2][128 * 40];

    const int n0 = blockIdx.x * 128, m0 = blockIdx.y * 128, d = blockIdx.z;
    const bf16* Wd = W + (size_t)d * G4 * KSZ;
    const int tid = threadIdx.x, w = tid >> 5, lane = tid & 31;
    const int gid = lane >> 2, tig = lane & 3;
    const int wm = (w & 3) * 32, wn = (w >> 2) * 64;

    float acc[2][8][4] = {};

    auto stage = [&](int c, int buf) {
        uint32_t sa = (uint32_t)__cvta_generic_to_shared(As[buf]);
        uint32_t sb = (uint32_t)__cvta_generic_to_shared(Bs[buf]);
#pragma unroll
        for (int p = 0; p < 2; p++) {
            int u = tid + p * 256;
            int row = u >> 2, c8 = (u & 3) * 8;
            cpa16(sa + (row * 40 + c8) * 2, X  + (size_t)(m0 + row) * KSZ + c * 32 + c8);
            cpa16(sb + (row * 40 + c8) * 2, Wd + (size_t)(n0 + row) * KSZ + c * 32 + c8);
        }
        CP_COMMIT;
    };

    stage(0, 0);
    stage(1, 1);

    for (int c = 0; c < NC; c++) {
        if (c + 1 == NC) { CP_WAIT(0); } else { CP_WAIT(1); }
        __syncthreads();
        const bf16* A  = As[c & 1];
        const bf16* Bm = Bs[c & 1];
#pragma unroll
        for (int ks = 0; ks < 2; ks++) {
            const int kk = ks * 16 + 2 * tig;
            uint32_t a[2][4];
#pragma unroll
            for (int mt = 0; mt < 2; mt++) {
                const bf16* ap = A + (wm + mt * 16 + gid) * 40;
                a[mt][0] = *(const uint32_t*)(ap + kk);
                a[mt][1] = *(const uint32_t*)(ap + 8 * 40 + kk);
                a[mt][2] = *(const uint32_t*)(ap + kk + 8);
                a[mt][3] = *(const uint32_t*)(ap + 8 * 40 + kk + 8);
            }
#pragma unroll
            for (int nt = 0; nt < 8; nt++) {
                const bf16* bp = Bm + (wn + nt * 8 + gid) * 40;
                uint32_t b0v = *(const uint32_t*)(bp + kk);
                uint32_t b1v = *(const uint32_t*)(bp + kk + 8);
                mma_bf(acc[0][nt], a[0][0], a[0][1], a[0][2], a[0][3], b0v, b1v);
                mma_bf(acc[1][nt], a[1][0], a[1][1], a[1][2], a[1][3], b0v, b1v);
            }
        }
        __syncthreads();
        if (c + 2 < NC) stage(c + 2, c & 1);
    }

    const float* bd = bias + (size_t)d * G4;
    float* outb = g_xp + (size_t)d * TB * G4;
#pragma unroll
    for (int mt = 0; mt < 2; mt++) {
        int r0 = m0 + wm + mt * 16 + gid;
#pragma unroll
        for (int nt = 0; nt < 8; nt++) {
            int col = n0 + wn + nt * 8 + 2 * tig;
            float bb0 = bd[col], bb1 = bd[col + 1];
            *(float2*)(outb + (size_t)r0 * G4 + col) =
                make_float2(acc[mt][nt][0] + bb0, acc[mt][nt][1] + bb1);
            *(float2*)(outb + (size_t)(r0 + 8) * G4 + col) =
                make_float2(acc[mt][nt][2] + bb0, acc[mt][nt][3] + bb1);
        }
    }
}

// ---------------- recurrence: 64 blocks/direction, 8 h-cols per block ----------
// z[b][g] = h[b][:] . Whh[g][:], bf16 mma; h bf16 [d][b][k]
// smem: whh 32x520 bf16 + h 64x520 bf16 + z 64x36 f32 = 109056 B
#define REC_SMEM ((32 * 520 + 64 * 520) * 2 + 64 * 36 * 4)

template<int L>
__global__ __launch_bounds__(256, 1) void rec_k(const bf16* __restrict__ Whh)
{
    bf16* Xout = L ? g_x2b : g_x1b;
    extern __shared__ char sm[];
    bf16*  whh_s = (bf16*)sm;                        // [32][520]
    bf16*  h_s   = (bf16*)(sm + 32 * 520 * 2);       // [64][520]
    float* z_s   = (float*)(sm + (32 + 64) * 520 * 2); // [64][36]
    uint32_t h_sa = (uint32_t)__cvta_generic_to_shared(h_s);

    const int blk = blockIdx.x, d = blk >> 6, jbase = (blk & 63) * 8;
    const int tid = threadIdx.x, w = tid >> 5, lane = tid & 31;
    const int gid = lane >> 2, tig = lane & 3;
    const int wmb = (w & 3) * 16, wng = (w >> 2) * 16;

    const bf16* Wd = Whh + (size_t)d * G4 * H_;
    // 32 gate rows this block owns: local gl = q*8+jl <-> global q*512 + jbase + jl
    for (int u = tid; u < 32 * 64; u += 256) {
        int gl = u >> 6, c8 = (u & 63) * 8;
        int grow = ((gl >> 3) << 9) + jbase + (gl & 7);
        *(uint4*)(whh_s + gl * 520 + c8) = *(const uint4*)(Wd + (size_t)grow * H_ + c8);
    }

    // cells: thread -> (b = tid>>2, j0 = (tid&3)*2), 2 cells each
    const int b = tid >> 2, j0 = (tid & 3) * 2;
    float cst[2] = {0.f, 0.f};
    const size_t hrow = ((size_t)d * B_ + b) * H_ + jbase + j0;
    *(__nv_bfloat162*)(g_hb + hrow) = __floats2bfloat162_rn(0.f, 0.f);

    unsigned bgen = 0;
    if (tid == 0) bgen = *((volatile unsigned*)&g_bar_gen[d]);
    gbarrier(d, bgen);

    const bf16* hsrc = g_hb + (size_t)d * B_ * H_;

    for (int s = 0; s < T_; s++) {
        const int t = d ? (T_ - 1 - s) : s;

        // stage full h (64x512) in two committed halves split along k
#pragma unroll
        for (int half = 0; half < 2; half++) {
#pragma unroll
            for (int p = 0; p < 8; p++) {
                int u = p * 256 + tid;
                int br = u >> 5, c8 = (u & 31) * 8;
                cpa16(h_sa + (br * 520 + half * 256 + c8) * 2,
                      hsrc + (size_t)br * H_ + half * 256 + c8);
            }
            CP_COMMIT;
        }

        // prefetch xp gates (fp32) for this thread's two cells
        const float* xpb = g_xp + ((size_t)(d * T_ + t) * B_ + b) * G4 + jbase + j0;
        float2 xq0 = *(const float2*)(xpb);
        float2 xq1 = *(const float2*)(xpb + 512);
        float2 xq2 = *(const float2*)(xpb + 1024);
        float2 xq3 = *(const float2*)(xpb + 1536);

        float z[2][4] = {};
#pragma unroll
        for (int half = 0; half < 2; half++) {
            if (half == 0) { CP_WAIT(1); } else { CP_WAIT(0); }
            __syncthreads();
#pragma unroll 4
            for (int ks = 0; ks < 16; ks++) {
                const int kk = half * 256 + ks * 16 + 2 * tig;
                uint32_t a0 = *(const uint32_t*)(h_s + (wmb + gid) * 520 + kk);
                uint32_t a1 = *(const uint32_t*)(h_s + (wmb + gid + 8) * 520 + kk);
                uint32_t a2 = *(const uint32_t*)(h_s + (wmb + gid) * 520 + kk + 8);
                uint32_t a3 = *(const uint32_t*)(h_s + (wmb + gid + 8) * 520 + kk + 8);
#pragma unroll
                for (int nt = 0; nt < 2; nt++) {
                    const bf16* bp = whh_s + (wng + nt * 8 + gid) * 520;
                    uint32_t b0v = *(const uint32_t*)(bp + kk);
                    uint32_t b1v = *(const uint32_t*)(bp + kk + 8);
                    mma_bf(z[nt], a0, a1, a2, a3, b0v, b1v);
                }
            }
        }

        // z fragments -> smem
#pragma unroll
        for (int nt = 0; nt < 2; nt++) {
            int cc = wng + nt * 8 + 2 * tig;
            *(float2*)&z_s[(wmb + gid) * 36 + cc]     = make_float2(z[nt][0], z[nt][1]);
            *(float2*)&z_s[(wmb + gid + 8) * 36 + cc] = make_float2(z[nt][2], z[nt][3]);
        }
        __syncthreads();

        // gates for cells (b, jbase+j0 / +1)   gate order: i,f,g,o
        float2 zi = *(float2*)&z_s[b * 36 +  0 + j0];
        float2 zf = *(float2*)&z_s[b * 36 +  8 + j0];
        float2 zg = *(float2*)&z_s[b * 36 + 16 + j0];
        float2 zo = *(float2*)&z_s[b * 36 + 24 + j0];
        float i0 = sigf(zi.x + xq0.x), i1 = sigf(zi.y + xq0.y);
        float f0 = sigf(zf.x + xq1.x), f1 = sigf(zf.y + xq1.y);
        float gg0 = tanhf(zg.x + xq2.x), gg1 = tanhf(zg.y + xq2.y);
        float o0 = sigf(zo.x + xq3.x), o1 = sigf(zo.y + xq3.y);
        cst[0] = f0 * cst[0] + i0 * gg0;
        cst[1] = f1 * cst[1] + i1 * gg1;
        float h0 = o0 * tanhf(cst[0]);
        float h1 = o1 * tanhf(cst[1]);
        __nv_bfloat162 hb = __floats2bfloat162_rn(h0, h1);
        *(__nv_bfloat162*)(g_hb + hrow) = hb;
        *(__nv_bfloat162*)(Xout + ((size_t)t * B_ + b) * (2 * H_) + d * H_ + jbase + j0) = hb;

        gbarrier(d, bgen);
    }
}

// ---------------- emission scores ----------------
__global__ __launch_bounds__(256) void feats_k(const float* __restrict__ lb)
{
    __shared__ float xs[8][129];
    __shared__ float ws[32][129];
    const int tid = threadIdx.x;
    const int r = tid >> 5, k = tid & 31;
    const size_t tb0 = (size_t)blockIdx.x * 8;
    float acc = 0.f;
    for (int c0 = 0; c0 < 2 * H_; c0 += 128) {
        for (int i = tid; i < 8 * 128; i += 256)
            xs[i >> 7][i & 127] = __bfloat162float(g_x2b[(tb0 + (i >> 7)) * (2 * H_) + c0 + (i & 127)]);
        for (int i = tid; i < 32 * 128; i += 256)
            ws[i >> 7][i & 127] = __bfloat162float(g_lwb[(size_t)(i >> 7) * (2 * H_) + c0 + (i & 127)]);
        __syncthreads();
#pragma unroll 16
        for (int kk = 0; kk < 128; kk++) acc += xs[r][kk] * ws[k][kk];
        __syncthreads();
    }
    g_feats[(tb0 + r) * KT + k] = acc + lb[k];
}

// ---------------- CRF: one warp per batch element ----------------
__global__ void crf_k(const int* __restrict__ tokens, const int* __restrict__ tags,
                      const int* __restrict__ lengths, const float* __restrict__ trans)
{
    const int b = blockIdx.x;
    const int k = threadIdx.x;              // 0..31
    __shared__ float al[KT];

    float tr[KT];
#pragma unroll
    for (int j = 0; j < KT; j++) tr[j] = trans[k * KT + j];

    al[k] = (k == 30) ? 0.f : NEGV;
    __syncwarp();

    for (int t = 0; t < T_; t++) {
        float m = -3.4e38f;
#pragma unroll
        for (int j = 0; j < KT; j++) m = fmaxf(m, al[j] + tr[j]);
        float ss = 0.f;
#pragma unroll
        for (int j = 0; j < KT; j++) ss += __expf(al[j] + tr[j] - m);
        float nw = m + __logf(ss) + g_feats[((size_t)t * B_ + b) * KT + k];
        int msk = tokens[t * B_ + b] > 0;
        __syncwarp();
        if (msk) al[k] = nw;
        __syncwarp();
    }

    float v = al[k] + trans[31 * KT + k];
    float m = v;
#pragma unroll
    for (int o = 16; o; o >>= 1) m = fmaxf(m, __shfl_xor_sync(0xffffffffu, m, o));
    float e = __expf(v - m);
#pragma unroll
    for (int o = 16; o; o >>= 1) e += __shfl_xor_sync(0xffffffffu, e, o);
    float logz = m + __logf(e);

    float gl = 0.f;
    for (int t = k; t < T_; t += 32) {
        int cur  = tags[t * B_ + b];
        int prev = (t == 0) ? 30 : tags[(t - 1) * B_ + b];
        float mm = (tokens[t * B_ + b] > 0) ? 1.f : 0.f;
        gl += mm * (trans[cur * KT + prev] + g_feats[((size_t)t * B_ + b) * KT + cur]);
    }
#pragma unroll
    for (int o = 16; o; o >>= 1) gl += __shfl_xor_sync(0xffffffffu, gl, o);
    gl += trans[31 * KT + tags[(T_ - 1) * B_ + b]];

    if (k == 0) g_part[b] = (logz - gl) / (float)lengths[b];
}

__global__ void out_k(float* __restrict__ out) {
    __shared__ float s[B_];
    s[threadIdx.x] = g_part[threadIdx.x];
    __syncthreads();
    for (int o = 32; o; o >>= 1) {
        if (threadIdx.x < o) s[threadIdx.x] += s[threadIdx.x + o];
        __syncthreads();
    }
    if (threadIdx.x == 0) out[0] = s[0];
}

// ---------------- launcher ----------------
extern "C" void kernel_launch(void* const* d_in, const int* in_sizes, int n_in,
                              void* d_out, int out_size)
{
    const int*   tokens  = (const int*)d_in[0];
    const int*   tags    = (const int*)d_in[1];
    const int*   lengths = (const int*)d_in[2];
    const float* embed   = (const float*)d_in[3];
    const float* wih0    = (const float*)d_in[4];
    const float* whh0    = (const float*)d_in[5];
    const float* b0      = (const float*)d_in[6];
    const float* wih1    = (const float*)d_in[7];
    const float* whh1    = (const float*)d_in[8];
    const float* b1      = (const float*)d_in[9];
    const float* lin_w   = (const float*)d_in[10];
    const float* lin_b   = (const float*)d_in[11];
    const float* trans   = (const float*)d_in[12];
    float* out = (float*)d_out;

    static bool attr_done = false;
    cudaFuncSetAttribute(rec_k<0>, cudaFuncAttributeMaxDynamicSharedMemorySize, REC_SMEM);
    cudaFuncSetAttribute(rec_k<1>, cudaFuncAttributeMaxDynamicSharedMemorySize, REC_SMEM);
    (void)attr_done;

    cvtall_k<<<10272, 256>>>(wih0, whh0, wih1, whh1, lin_w);
    embed_k<<<8192, 256>>>(tokens, embed);

    gemm_k<0><<<dim3(16, 128, 2), 256>>>(g_wih0b, b0);
    rec_k<0><<<128, 256, REC_SMEM>>>(g_whh0b);

    gemm_k<1><<<dim3(16, 128, 2), 256>>>(g_wih1b, b1);
    rec_k<1><<<128, 256, REC_SMEM>>>(g_whh1b);

    feats_k<<<TB / 8, 256>>>(lin_b);
    crf_k<<<B_, 32>>>(tokens, tags, lengths, trans);
    out_k<<<1, B_>>>(out);
}